// round 10
// baseline (speedup 1.0000x reference)
#include <cuda_runtime.h>

#define SS     256
#define BB     64
#define INF    256
#define HH     256
#define INNER  512
#define AA     64
#define LEVELS 7
#define NB     126
#define NT     256
#define NSUPER (SS + 2 * (LEVELS - 1))   // 268

// smem (floats): wP[512k][32c] pair-interleaved @0 ; wB1[512k][16c] pair @16384 ;
// gates 3*64 @24576 ; swa3[64] @24768 ; sb1[16] @24832 ; sbias1[32] @24848
#define OFF_WB1   16384
#define OFF_SG    24576
#define OFF_WA3   24768
#define OFF_B1    24832
#define OFF_BIAS1 24848
#define SMEM_FLOATS 24896
#define SMEM_BYTES  (SMEM_FLOATS * 4)

__device__ float g_xe[SS * BB * HH];
__device__ float g_dm[SS * BB];
__device__ float g_tmpL[LEVELS][BB * INNER];
__device__ float g_aL[LEVELS][BB * AA];
__device__ float r_xv[LEVELS][4][BB * HH];
__device__ float r_nm[LEVELS][4][BB];
__device__ float r_hv[LEVELS][4][BB];

__device__ volatile unsigned g_arrive[NB];
__device__ volatile unsigned g_gen = 0;

__device__ __forceinline__ void gbar(unsigned ep) {
    __syncthreads();
    if (blockIdx.x == 0) {
        int tid = threadIdx.x;
        if (tid >= 1 && tid < NB) {
            while (g_arrive[tid] < ep) { }
        }
        __syncthreads();
        if (tid == 0) { __threadfence(); g_gen = ep; }
        __syncthreads();
    } else {
        if (threadIdx.x == 0) {
            __threadfence();                 // release: data -> L2 before arrival
            g_arrive[blockIdx.x] = ep;
            while (g_gen < ep) { }           // strong poll; mutable reads use .cg
        }
        __syncthreads();
    }
}

__device__ __forceinline__ float lrelu(float z) { return z >= 0.f ? z : 0.01f * z; }

__device__ __forceinline__ void ffma2(unsigned long long& d, unsigned long long a,
                                      unsigned long long b) {
    asm("fma.rn.f32x2 %0, %1, %2, %0;" : "+l"(d) : "l"(a), "l"(b));
}
__device__ __forceinline__ float padd(unsigned long long v) {
    float lo, hi;
    asm("mov.b64 {%0, %1}, %2;" : "=f"(lo), "=f"(hi) : "l"(v));
    return lo + hi;
}

// K=256 chunk: 8 sample rows (stride RS, L2 via ldcg), 32 pair-interleaved smem
// weight cols. Thread = (kh in {0,1}, q in [0,16)): 128 k x 2 cols, acc pairs over k.
template<long RS>
__device__ __forceinline__ void gemm2_half(const float* __restrict__ src0,
                                           const float* __restrict__ wps,
                                           int kh, int q,
                                           unsigned long long acc[8][2]) {
    #pragma unroll 2
    for (int j = 0; j < 32; j++) {
        const int k  = kh * 128 + j * 4;
        const int k2 = k >> 1;
        float4 av[8];
        #pragma unroll
        for (int s = 0; s < 8; s++)
            av[s] = __ldcg((const float4*)(src0 + (long)s * RS + k));
        ulonglong2 w0 = *(const ulonglong2*)(wps + (k2)     * 64 + q * 4);
        ulonglong2 w1 = *(const ulonglong2*)(wps + (k2 + 1) * 64 + q * 4);
        #pragma unroll
        for (int s = 0; s < 8; s++) {
            ulonglong2 a2 = *(const ulonglong2*)&av[s];
            ffma2(acc[s][0], a2.x, w0.x);
            ffma2(acc[s][1], a2.x, w0.y);
            ffma2(acc[s][0], a2.y, w1.x);
            ffma2(acc[s][1], a2.y, w1.y);
        }
    }
}

__global__ void __launch_bounds__(NT, 1)
enc_kernel(const float* __restrict__ x, const float* __restrict__ mask,
           const float* __restrict__ W_emb, const float* __restrict__ b_emb,
           const float* __restrict__ W, const float* __restrict__ U, const float* __restrict__ b,
           const float* __restrict__ W1, const float* __restrict__ b1,
           const float* __restrict__ Wa1, const float* __restrict__ Ua1, const float* __restrict__ ba1,
           const float* __restrict__ Wa3, const float* __restrict__ ba3,
           float* __restrict__ out)
{
    extern __shared__ float smem[];
    float* const wP     = smem;                  // [512][32] pair-interleaved
    float* const wB1    = smem + OFF_WB1;        // [512][16] pair-interleaved
    float* const sgb    = smem + OFF_SG;
    float* const sgx    = smem + OFF_SG + 64;
    float* const sgh    = smem + OFF_SG + 128;
    float* const swa3   = smem + OFF_WA3;
    float* const sb1    = smem + OFF_B1;
    float* const sbias1 = smem + OFF_BIAS1;

    const int tid = threadIdx.x, bid = blockIdx.x;
    const int w = tid >> 5, lane = tid & 31;
    unsigned ep = g_gen;

    const int lvl1 = bid / 18, cb1 = (bid % 18) * 32;
    const bool p2on = bid < 112;
    const int lvl2 = bid >> 4, cb2 = (bid & 15) * 16;

    // ---- init dm + ring zero ----
    for (int idx = bid * NT + tid; idx < SS * BB; idx += NB * NT) {
        int t = idx >> 6, i = idx & 63;
        g_dm[idx] = mask[i * SS + t];
    }
    for (int idx = bid * NT + tid; idx < LEVELS * BB * HH; idx += NB * NT)
        r_xv[idx >> 14][3][idx & 16383] = 0.f;
    for (int idx = bid * NT + tid; idx < LEVELS * BB; idx += NB * NT)
        r_hv[idx >> 6][3][idx & 63] = 0.f;

    // ---- embedding (120 blocks: 8 col-slices x 15 t-groups) ----
    if (bid < 120) {
        const int esl = bid & 7, egr = bid >> 3;
        for (int idx = tid; idx < 256 * 32; idx += NT) {
            int k = idx >> 5, cc = idx & 31;
            wP[(k >> 1) * 64 + (cc >> 1) * 4 + (cc & 1) * 2 + (k & 1)] =
                W_emb[k * HH + esl * 32 + cc];
        }
        __syncthreads();
        const int kh = lane >> 4, q = lane & 15;
        for (int n = egr; n < SS; n += 15) {
            const int ib = 8 * w;
            unsigned long long acc[8][2];
            #pragma unroll
            for (int s = 0; s < 8; s++) { acc[s][0] = 0ULL; acc[s][1] = 0ULL; }
            gemm2_half<(long)SS * INF>(x + ((long)ib * SS + n) * INF, wP, kh, q, acc);
            float r0[8], r1[8];
            #pragma unroll
            for (int s = 0; s < 8; s++) {
                r0[s] = padd(acc[s][0]); r1[s] = padd(acc[s][1]);
                r0[s] += __shfl_xor_sync(0xffffffffu, r0[s], 16);
                r1[s] += __shfl_xor_sync(0xffffffffu, r1[s], 16);
            }
            if (lane < 16) {
                int col = esl * 32 + q * 2;
                float2 be = *(const float2*)&b_emb[col];
                #pragma unroll
                for (int s = 0; s < 8; s++) {
                    float2 o = make_float2(r0[s] + be.x, r1[s] + be.y);
                    *(float2*)&g_xe[((long)n * BB + ib + s) * HH + col] = o;
                }
            }
        }
        __syncthreads();
    }

    // ---- stage persistent weights (pair-interleaved) ----
    for (int idx = tid; idx < 512 * 32; idx += NT) {
        int k = idx >> 5, cc = idx & 31, col = cb1 + cc;
        float v;
        if (col < 512) v = (k < 256) ? W[k * INNER + col] : U[(k - 256) * INNER + col];
        else { int a = col - 512; v = (k < 256) ? Wa1[k * AA + a] : Ua1[(k - 256) * AA + a]; }
        wP[(k >> 1) * 64 + (cc >> 1) * 4 + (cc & 1) * 2 + (k & 1)] = v;
    }
    if (p2on) {
        for (int idx = tid; idx < 512 * 16; idx += NT) {
            int k = idx >> 4, cc = idx & 15;
            wB1[(k >> 1) * 32 + (cc >> 1) * 4 + (cc & 1) * 2 + (k & 1)] =
                W1[k * HH + cb2 + cc];
        }
        if (tid < 16) sb1[tid] = b1[cb2 + tid];
    }
    if (tid < 64) swa3[tid] = Wa3[tid];
    if (tid < 32) {
        int col = cb1 + tid;
        sbias1[tid] = (col < 512) ? b[col] : ba1[col - 512];
    }
    const float ba3v = __ldg(ba3);
    gbar(++ep);

    // ---- wavefront supersteps ----
    for (int u = 0; u < NSUPER; u++) {
        // ======== phase 1: [tmp|a] = lrelu([xt|h] @ [W;U|Wa1;Ua1] + bias) ========
        const int t1 = u - 2 * lvl1;
        if ((unsigned)t1 < SS) {
            const float* xt = (lvl1 == 0) ? &g_xe[(long)t1 * BB * HH]
                                          : r_xv[lvl1 - 1][t1 & 3];
            const float* hp = r_xv[lvl1][(t1 + 3) & 3];
            const int kh = lane >> 4, q = lane & 15, ib = 8 * w;
            unsigned long long acc[8][2];
            #pragma unroll
            for (int s = 0; s < 8; s++) { acc[s][0] = 0ULL; acc[s][1] = 0ULL; }
            gemm2_half<HH>(xt + (long)ib * HH, wP,            kh, q, acc);
            gemm2_half<HH>(hp + (long)ib * HH, wP + 256 * 32, kh, q, acc);
            float r0[8], r1[8];
            #pragma unroll
            for (int s = 0; s < 8; s++) {
                r0[s] = padd(acc[s][0]); r1[s] = padd(acc[s][1]);
                r0[s] += __shfl_xor_sync(0xffffffffu, r0[s], 16);
                r1[s] += __shfl_xor_sync(0xffffffffu, r1[s], 16);
            }
            if (lane < 16) {
                const int c0 = cb1 + q * 2;
                float2 bv = *(const float2*)&sbias1[q * 2];
                #pragma unroll
                for (int s = 0; s < 8; s++) {
                    int i = ib + s;
                    float2 o = make_float2(lrelu(r0[s] + bv.x), lrelu(r1[s] + bv.y));
                    if (c0 < 512) *(float2*)&g_tmpL[lvl1][i * INNER + c0] = o;
                    else          *(float2*)&g_aL[lvl1][i * AA + c0 - 512] = o;
                }
            }
        }
        gbar(++ep);

        // ======== phase 2: gates + h = g(lrelu(tmp @ W1 + b1), xt, h_old) ========
        const int t2 = u - 2 * lvl2;
        if (p2on && (unsigned)t2 < SS) {
            {   // gate scalars
                int i = tid >> 2, qtr = tid & 3;
                const float* ar = &g_aL[lvl2][i * AA + qtr * 16];
                float p = 0.f;
                #pragma unroll
                for (int c = 0; c < 16; c += 4) {
                    float4 a4 = __ldcg((const float4*)&ar[c]);
                    float4 w4 = *(const float4*)&swa3[qtr * 16 + c];
                    p += a4.x * w4.x + a4.y * w4.y + a4.z * w4.z + a4.w * w4.w;
                }
                p += __shfl_xor_sync(0xffffffffu, p, 1);
                p += __shfl_xor_sync(0xffffffffu, p, 2);
                if (qtr == 0) {
                    float sg  = 0.2f * (p + ba3v) + 0.5f;
                    float nmr = fminf(fmaxf(sg, 0.f), 1.f);
                    float lv  = (t2 == SS - 1) ? 1.f : 0.f;
                    float pm, ph;
                    if (lvl2 == 0) { pm = g_dm[t2 * BB + i]; ph = pm; }
                    else {
                        pm = (t2 == SS - 1) ? 1.f : __ldcg(&r_nm[lvl2 - 1][(t2 + 1) & 3][i]);
                        ph = __ldcg(&r_hv[lvl2 - 1][t2 & 3][i]);
                    }
                    float hvp = __ldcg(&r_hv[lvl2][(t2 + 3) & 3][i]);
                    float nm   = (1.f - lv) * (pm * ph * nmr);
                    float both = pm * ph * (1.f - nm) * hvp;
                    float xo   = pm * ph * (nm + (1.f - nm) * (1.f - hvp));
                    float ho   = (1.f - pm + pm * (1.f - ph)) * (1.f - nm) * hvp;
                    sgb[i] = both; sgx[i] = xo; sgh[i] = ho;
                    r_nm[lvl2][t2 & 3][i] = nm;
                    r_hv[lvl2][t2 & 3][i] = both + xo + ho;
                }
            }
            __syncthreads();
            // B GEMM: K=512, 16 cols; thread = (kq in [0,4), q in [0,8)): 2 cols
            const float* tl = g_tmpL[lvl2];
            const int kq = lane >> 3, q = lane & 7, ib = 8 * w;
            unsigned long long acc[8][2];
            #pragma unroll
            for (int s = 0; s < 8; s++) { acc[s][0] = 0ULL; acc[s][1] = 0ULL; }
            #pragma unroll 2
            for (int j = 0; j < 32; j++) {
                const int k = kq * 128 + j * 4;
                const int k2 = k >> 1;
                float4 tv[8];
                #pragma unroll
                for (int s = 0; s < 8; s++)
                    tv[s] = __ldcg((const float4*)(tl + (long)(ib + s) * INNER + k));
                ulonglong2 w0 = *(const ulonglong2*)(wB1 + (k2)     * 32 + q * 4);
                ulonglong2 w1 = *(const ulonglong2*)(wB1 + (k2 + 1) * 32 + q * 4);
                #pragma unroll
                for (int s = 0; s < 8; s++) {
                    ulonglong2 a2 = *(const ulonglong2*)&tv[s];
                    ffma2(acc[s][0], a2.x, w0.x);
                    ffma2(acc[s][1], a2.x, w0.y);
                    ffma2(acc[s][0], a2.y, w1.x);
                    ffma2(acc[s][1], a2.y, w1.y);
                }
            }
            float r0[8], r1[8];
            #pragma unroll
            for (int s = 0; s < 8; s++) {
                r0[s] = padd(acc[s][0]); r1[s] = padd(acc[s][1]);
                r0[s] += __shfl_xor_sync(0xffffffffu, r0[s], 8);
                r1[s] += __shfl_xor_sync(0xffffffffu, r1[s], 8);
                r0[s] += __shfl_xor_sync(0xffffffffu, r0[s], 16);
                r1[s] += __shfl_xor_sync(0xffffffffu, r1[s], 16);
            }
            if (lane < 8) {
                const int c0 = cb2 + q * 2;
                float2 b1v = *(const float2*)&sb1[q * 2];
                const float* xtp = (lvl2 == 0) ? &g_xe[(long)t2 * BB * HH]
                                               : r_xv[lvl2 - 1][t2 & 3];
                const float* hop = r_xv[lvl2][(t2 + 3) & 3];
                float* hnp = r_xv[lvl2][t2 & 3];
                #pragma unroll
                for (int s = 0; s < 8; s++) {
                    int i = ib + s;
                    float h0 = lrelu(r0[s] + b1v.x);
                    float h1 = lrelu(r1[s] + b1v.y);
                    float bo = sgb[i], xo = sgx[i], ho = sgh[i];
                    float2 xt2 = __ldcg((const float2*)&xtp[i * HH + c0]);
                    float2 hl2 = __ldcg((const float2*)&hop[i * HH + c0]);
                    float2 hn;
                    hn.x = bo * h0 + xo * xt2.x + ho * hl2.x;
                    hn.y = bo * h1 + xo * xt2.y + ho * hl2.y;
                    *(float2*)&hnp[i * HH + c0] = hn;
                    if (lvl2 == LEVELS - 1 && t2 == SS - 1)
                        *(float2*)&out[i * HH + c0] = hn;
                }
            }
        }
        gbar(++ep);
    }
}

extern "C" void kernel_launch(void* const* d_in, const int* in_sizes, int n_in,
                              void* d_out, int out_size) {
    const float* x     = (const float*)d_in[0];
    const float* mask  = (const float*)d_in[1];
    const float* W_emb = (const float*)d_in[3];
    const float* b_emb = (const float*)d_in[4];
    const float* W     = (const float*)d_in[5];
    const float* U     = (const float*)d_in[6];
    const float* b     = (const float*)d_in[7];
    const float* W1    = (const float*)d_in[8];
    const float* b1    = (const float*)d_in[9];
    const float* Wa1   = (const float*)d_in[10];
    const float* Ua1   = (const float*)d_in[11];
    const float* ba1   = (const float*)d_in[12];
    const float* Wa3   = (const float*)d_in[13];
    const float* ba3   = (const float*)d_in[14];
    float* out = (float*)d_out;

    cudaFuncSetAttribute(enc_kernel, cudaFuncAttributeMaxDynamicSharedMemorySize, SMEM_BYTES);
    enc_kernel<<<NB, NT, SMEM_BYTES>>>(x, mask, W_emb, b_emb, W, U, b, W1, b1,
                                       Wa1, Ua1, ba1, Wa3, ba3, out);
}

// round 11
// speedup vs baseline: 1.0629x; 1.0629x over previous
#include <cuda_runtime.h>

#define SS     256
#define BB     64
#define INF    256
#define HH     256
#define INNER  512
#define AA     64
#define LEVELS 7
#define NB     126
#define NT     512
#define NSUPER (SS + 2 * (LEVELS - 1))   // 268

// smem (floats): wP[512][32] @0 ; wB1[512][16] @16384 ; gates 3*64 @24576 ;
//                swa3[64] @24768 ; sb1[16] @24832 ; sbias1[32] @24848
#define OFF_WB1   16384
#define OFF_SG    24576
#define OFF_WA3   24768
#define OFF_B1    24832
#define OFF_BIAS1 24848
#define SMEM_FLOATS 24896
#define SMEM_BYTES  (SMEM_FLOATS * 4)

__device__ float g_xe[SS * BB * HH];
__device__ float g_dm[SS * BB];
__device__ float g_tmpL[LEVELS][BB * INNER];
__device__ float g_aL[LEVELS][BB * AA];
__device__ float r_xv[LEVELS][4][BB * HH];
__device__ float r_nm[LEVELS][4][BB];
__device__ float r_hv[LEVELS][4][BB];

__device__ volatile unsigned g_arrive[NB];
__device__ volatile unsigned g_gen = 0;

__device__ __forceinline__ void gbar(unsigned ep) {
    __syncthreads();
    if (blockIdx.x == 0) {
        int tid = threadIdx.x;
        if (tid >= 1 && tid < NB) {
            while (g_arrive[tid] < ep) { }
        }
        __syncthreads();
        if (tid == 0) { __threadfence(); g_gen = ep; }
        __syncthreads();
    } else {
        if (threadIdx.x == 0) {
            __threadfence();                 // release
            g_arrive[blockIdx.x] = ep;
            while (g_gen < ep) { }
            __threadfence();                 // acquire
        }
        __syncthreads();
    }
}

__device__ __forceinline__ float lrelu(float z) { return z >= 0.f ? z : 0.01f * z; }

__device__ __forceinline__ void fma4(float4& a, float s, const float4& v) {
    a.x = fmaf(s, v.x, a.x); a.y = fmaf(s, v.y, a.y);
    a.z = fmaf(s, v.z, a.z); a.w = fmaf(s, v.w, a.w);
}
__device__ __forceinline__ float fcomp(const float4& v, int k) {
    return k == 0 ? v.x : k == 1 ? v.y : k == 2 ? v.z : v.w;
}
__device__ __forceinline__ void red4(float4& a, int m) {
    a.x += __shfl_xor_sync(0xffffffffu, a.x, m);
    a.y += __shfl_xor_sync(0xffffffffu, a.y, m);
    a.z += __shfl_xor_sync(0xffffffffu, a.z, m);
    a.w += __shfl_xor_sync(0xffffffffu, a.w, m);
}

// K=256 half: 4 samples (row stride RS, __ldg), 32 smem weight cols.
// Thread = (kq in [0,4), q in [0,8)); each kq owns 64 k's; acc[4] = 4 samples x 4 cols.
template<long RS>
__device__ __forceinline__ void gemmA_half(const float* __restrict__ src0,
                                           const float* __restrict__ wcol,
                                           int kq, int q, float4 acc[4]) {
    #pragma unroll 4
    for (int j = 0; j < 16; j++) {
        const int k = kq * 64 + j * 4;
        float4 av[4];
        #pragma unroll
        for (int s = 0; s < 4; s++)
            av[s] = __ldg((const float4*)(src0 + (long)s * RS + k));
        #pragma unroll
        for (int kk = 0; kk < 4; kk++) {
            float4 wv = *(const float4*)(wcol + (k + kk) * 32 + q * 4);
            #pragma unroll
            for (int s = 0; s < 4; s++) fma4(acc[s], fcomp(av[s], kk), wv);
        }
    }
}

__global__ void __launch_bounds__(NT, 1)
enc_kernel(const float* __restrict__ x, const float* __restrict__ mask,
           const float* __restrict__ W_emb, const float* __restrict__ b_emb,
           const float* __restrict__ W, const float* __restrict__ U, const float* __restrict__ b,
           const float* __restrict__ W1, const float* __restrict__ b1,
           const float* __restrict__ Wa1, const float* __restrict__ Ua1, const float* __restrict__ ba1,
           const float* __restrict__ Wa3, const float* __restrict__ ba3,
           float* __restrict__ out)
{
    extern __shared__ float smem[];
    float* const wP     = smem;                  // [512][32]
    float* const wB1    = smem + OFF_WB1;        // [512][16]
    float* const sgb    = smem + OFF_SG;
    float* const sgx    = smem + OFF_SG + 64;
    float* const sgh    = smem + OFF_SG + 128;
    float* const swa3   = smem + OFF_WA3;
    float* const sb1    = smem + OFF_B1;
    float* const sbias1 = smem + OFF_BIAS1;

    const int tid = threadIdx.x, bid = blockIdx.x;
    const int w = tid >> 5, lane = tid & 31;
    unsigned ep = g_gen;

    const int lvl1 = bid / 18, cb1 = (bid % 18) * 32;
    const bool p2on = bid < 112;
    const int lvl2 = bid >> 4, cb2 = (bid & 15) * 16;

    // ---- init dm + ring zero ----
    for (int idx = bid * NT + tid; idx < SS * BB; idx += NB * NT) {
        int t = idx >> 6, i = idx & 63;
        g_dm[idx] = mask[i * SS + t];
    }
    for (int idx = bid * NT + tid; idx < LEVELS * BB * HH; idx += NB * NT)
        r_xv[idx >> 14][3][idx & 16383] = 0.f;
    for (int idx = bid * NT + tid; idx < LEVELS * BB; idx += NB * NT)
        r_hv[idx >> 6][3][idx & 63] = 0.f;

    // ---- embedding (120 blocks: 8 col-slices x 15 t-groups) ----
    if (bid < 120) {
        const int esl = bid & 7, egr = bid >> 3;
        for (int idx = tid; idx < 256 * 32; idx += NT) {
            int k = idx >> 5, c = idx & 31;
            wP[idx] = W_emb[k * HH + esl * 32 + c];
        }
        __syncthreads();
        const int kq = lane >> 3, q = lane & 7;
        for (int n = egr; n < SS; n += 15) {
            const int ib = 4 * w;
            float4 acc[4];
            #pragma unroll
            for (int s = 0; s < 4; s++) acc[s] = make_float4(0.f, 0.f, 0.f, 0.f);
            gemmA_half<(long)SS * INF>(x + ((long)ib * SS + n) * INF, wP, kq, q, acc);
            #pragma unroll
            for (int s = 0; s < 4; s++) { red4(acc[s], 8); red4(acc[s], 16); }
            if (lane < 8) {
                int col = esl * 32 + lane * 4;
                float4 be = __ldg((const float4*)&b_emb[col]);
                #pragma unroll
                for (int s = 0; s < 4; s++) {
                    float4 o = acc[s];
                    o.x += be.x; o.y += be.y; o.z += be.z; o.w += be.w;
                    *(float4*)&g_xe[((long)n * BB + ib + s) * HH + col] = o;
                }
            }
        }
        __syncthreads();
    }

    // ---- stage persistent weights ----
    for (int idx = tid; idx < 512 * 32; idx += NT) {
        int k = idx >> 5, col = cb1 + (idx & 31);
        float v;
        if (col < 512) v = (k < 256) ? W[k * INNER + col] : U[(k - 256) * INNER + col];
        else { int a = col - 512; v = (k < 256) ? Wa1[k * AA + a] : Ua1[(k - 256) * AA + a]; }
        wP[idx] = v;
    }
    if (p2on) {
        for (int idx = tid; idx < 512 * 16; idx += NT)
            wB1[idx] = W1[(idx >> 4) * HH + cb2 + (idx & 15)];
        if (tid < 16) sb1[tid] = b1[cb2 + tid];
    }
    if (tid < 64) swa3[tid] = Wa3[tid];
    if (tid < 32) {
        int col = cb1 + tid;
        sbias1[tid] = (col < 512) ? b[col] : ba1[col - 512];
    }
    const float ba3v = __ldg(ba3);
    gbar(++ep);

    // ---- wavefront supersteps ----
    for (int u = 0; u < NSUPER; u++) {
        // ======== phase 1: [tmp|a] = lrelu([xt|h] @ [W;U|Wa1;Ua1] + bias) ========
        const int t1 = u - 2 * lvl1;
        if ((unsigned)t1 < SS) {
            const float* xt = (lvl1 == 0) ? &g_xe[(long)t1 * BB * HH]
                                          : r_xv[lvl1 - 1][t1 & 3];
            const float* hp = r_xv[lvl1][(t1 + 3) & 3];
            const int kq = lane >> 3, q = lane & 7, ib = 4 * w;
            float4 acc[4];
            #pragma unroll
            for (int s = 0; s < 4; s++) acc[s] = make_float4(0.f, 0.f, 0.f, 0.f);
            gemmA_half<HH>(xt + (long)ib * HH, wP,            kq, q, acc);
            gemmA_half<HH>(hp + (long)ib * HH, wP + 256 * 32, kq, q, acc);
            #pragma unroll
            for (int s = 0; s < 4; s++) { red4(acc[s], 8); red4(acc[s], 16); }
            if (lane < 8) {
                const int col = cb1 + lane * 4;
                float4 bv = *(const float4*)&sbias1[lane * 4];
                #pragma unroll
                for (int s = 0; s < 4; s++) {
                    int i = ib + s;
                    float4 o;
                    o.x = lrelu(acc[s].x + bv.x); o.y = lrelu(acc[s].y + bv.y);
                    o.z = lrelu(acc[s].z + bv.z); o.w = lrelu(acc[s].w + bv.w);
                    if (col < 512) *(float4*)&g_tmpL[lvl1][i * INNER + col] = o;
                    else           *(float4*)&g_aL[lvl1][i * AA + col - 512] = o;
                }
            }
        }
        gbar(++ep);

        // ======== phase 2: gates + h = g(lrelu(tmp @ W1 + b1), xt, h_old) ========
        const int t2 = u - 2 * lvl2;
        if (p2on && (unsigned)t2 < SS) {
            {   // gate scalars: i = tid>>3, 8-lane dot split
                int i = tid >> 3, qtr = tid & 7;
                const float* ar = &g_aL[lvl2][i * AA + qtr * 8];
                float p = 0.f;
                #pragma unroll
                for (int c = 0; c < 8; c += 4) {
                    float4 a4 = __ldg((const float4*)&ar[c]);
                    float4 w4 = *(const float4*)&swa3[qtr * 8 + c];
                    p += a4.x * w4.x + a4.y * w4.y + a4.z * w4.z + a4.w * w4.w;
                }
                p += __shfl_xor_sync(0xffffffffu, p, 1);
                p += __shfl_xor_sync(0xffffffffu, p, 2);
                p += __shfl_xor_sync(0xffffffffu, p, 4);
                if (qtr == 0) {
                    float sg  = 0.2f * (p + ba3v) + 0.5f;
                    float nmr = fminf(fmaxf(sg, 0.f), 1.f);
                    float lv  = (t2 == SS - 1) ? 1.f : 0.f;
                    float pm, ph;
                    if (lvl2 == 0) { pm = g_dm[t2 * BB + i]; ph = pm; }
                    else {
                        pm = (t2 == SS - 1) ? 1.f : r_nm[lvl2 - 1][(t2 + 1) & 3][i];
                        ph = r_hv[lvl2 - 1][t2 & 3][i];
                    }
                    float hvp = r_hv[lvl2][(t2 + 3) & 3][i];
                    float nm   = (1.f - lv) * (pm * ph * nmr);
                    float both = pm * ph * (1.f - nm) * hvp;
                    float xo   = pm * ph * (nm + (1.f - nm) * (1.f - hvp));
                    float ho   = (1.f - pm + pm * (1.f - ph)) * (1.f - nm) * hvp;
                    sgb[i] = both; sgx[i] = xo; sgh[i] = ho;
                    r_nm[lvl2][t2 & 3][i] = nm;
                    r_hv[lvl2][t2 & 3][i] = both + xo + ho;
                }
            }
            __syncthreads();
            // B GEMM: K=512, 16 cols; thread = (kq in [0,8), q in [0,4)), 4 samples
            const float* tl = g_tmpL[lvl2];
            const int kq = lane >> 2, q = lane & 3, ib = 4 * w;
            float4 acc[4];
            #pragma unroll
            for (int s = 0; s < 4; s++) acc[s] = make_float4(0.f, 0.f, 0.f, 0.f);
            #pragma unroll 4
            for (int j = 0; j < 16; j++) {
                const int k = kq * 64 + j * 4;
                float4 tv[4];
                #pragma unroll
                for (int s = 0; s < 4; s++)
                    tv[s] = __ldg((const float4*)(tl + (long)(ib + s) * INNER + k));
                #pragma unroll
                for (int kk = 0; kk < 4; kk++) {
                    float4 wv = *(const float4*)&wB1[(k + kk) * 16 + q * 4];
                    #pragma unroll
                    for (int s = 0; s < 4; s++) fma4(acc[s], fcomp(tv[s], kk), wv);
                }
            }
            #pragma unroll
            for (int s = 0; s < 4; s++) { red4(acc[s], 4); red4(acc[s], 8); red4(acc[s], 16); }
            if (lane < 4) {
                const int col = cb2 + lane * 4;
                float4 b1v = *(const float4*)&sb1[lane * 4];
                const float* xtp = (lvl2 == 0) ? &g_xe[(long)t2 * BB * HH]
                                               : r_xv[lvl2 - 1][t2 & 3];
                const float* hop = r_xv[lvl2][(t2 + 3) & 3];
                float* hnp = r_xv[lvl2][t2 & 3];
                #pragma unroll
                for (int s = 0; s < 4; s++) {
                    int i = ib + s;
                    float h0 = lrelu(acc[s].x + b1v.x);
                    float h1 = lrelu(acc[s].y + b1v.y);
                    float h2 = lrelu(acc[s].z + b1v.z);
                    float h3 = lrelu(acc[s].w + b1v.w);
                    float bo = sgb[i], xo = sgx[i], ho = sgh[i];
                    float4 xt4 = __ldg((const float4*)&xtp[i * HH + col]);
                    float4 hl4 = __ldg((const float4*)&hop[i * HH + col]);
                    float4 hn;
                    hn.x = bo * h0 + xo * xt4.x + ho * hl4.x;
                    hn.y = bo * h1 + xo * xt4.y + ho * hl4.y;
                    hn.z = bo * h2 + xo * xt4.z + ho * hl4.z;
                    hn.w = bo * h3 + xo * xt4.w + ho * hl4.w;
                    *(float4*)&hnp[i * HH + col] = hn;
                    if (lvl2 == LEVELS - 1 && t2 == SS - 1)
                        *(float4*)&out[i * HH + col] = hn;
                }
            }
        }
        gbar(++ep);
    }
}

extern "C" void kernel_launch(void* const* d_in, const int* in_sizes, int n_in,
                              void* d_out, int out_size) {
    const float* x     = (const float*)d_in[0];
    const float* mask  = (const float*)d_in[1];
    const float* W_emb = (const float*)d_in[3];
    const float* b_emb = (const float*)d_in[4];
    const float* W     = (const float*)d_in[5];
    const float* U     = (const float*)d_in[6];
    const float* b     = (const float*)d_in[7];
    const float* W1    = (const float*)d_in[8];
    const float* b1    = (const float*)d_in[9];
    const float* Wa1   = (const float*)d_in[10];
    const float* Ua1   = (const float*)d_in[11];
    const float* ba1   = (const float*)d_in[12];
    const float* Wa3   = (const float*)d_in[13];
    const float* ba3   = (const float*)d_in[14];
    float* out = (float*)d_out;

    cudaFuncSetAttribute(enc_kernel, cudaFuncAttributeMaxDynamicSharedMemorySize, SMEM_BYTES);
    enc_kernel<<<NB, NT, SMEM_BYTES>>>(x, mask, W_emb, b_emb, W, U, b, W1, b1,
                                       Wa1, Ua1, ba1, Wa3, ba3, out);
}

// round 12
// speedup vs baseline: 1.0966x; 1.0318x over previous
#include <cuda_runtime.h>

#define SS     256
#define BB     64
#define INF    256
#define HH     256
#define INNER  512
#define AA     64
#define LEVELS 7
#define NB     126
#define NT     512
#define NSUPER (SS + 2 * (LEVELS - 1))   // 268

// smem (floats): wP[512][32] @0 ; wB1[512][16] @16384 ; gates 3*64 @24576 ;
//                swa3[64] @24768 ; sb1[16] @24832 ; sbias1[32] @24848
#define OFF_WB1   16384
#define OFF_SG    24576
#define OFF_WA3   24768
#define OFF_B1    24832
#define OFF_BIAS1 24848
#define SMEM_FLOATS 24896
#define SMEM_BYTES  (SMEM_FLOATS * 4)

__device__ float g_xe[SS * BB * HH];
__device__ float g_dm[SS * BB];
__device__ float g_tmpL[LEVELS][BB * INNER];
__device__ float g_aL[LEVELS][BB * AA];
__device__ float r_xv[LEVELS][4][BB * HH];
__device__ float r_nm[LEVELS][4][BB];
__device__ float r_hv[LEVELS][4][BB];

__device__ volatile unsigned g_arrive[NB];
__device__ volatile unsigned g_gen = 0;

__device__ __forceinline__ void gbar(unsigned ep) {
    __syncthreads();
    if (blockIdx.x == 0) {
        int tid = threadIdx.x;
        if (tid >= 1 && tid < NB) {
            while (g_arrive[tid] < ep) { }
        }
        __syncthreads();
        if (tid == 0) { __threadfence(); g_gen = ep; }
        __syncthreads();
    } else {
        if (threadIdx.x == 0) {
            __threadfence();                 // release
            g_arrive[blockIdx.x] = ep;
            while (g_gen < ep) { }
            __threadfence();                 // acquire (SM-wide L1 invalidate)
        }
        __syncthreads();
    }
}

__device__ __forceinline__ float lrelu(float z) { return z >= 0.f ? z : 0.01f * z; }

__device__ __forceinline__ void fma4(float4& a, float s, const float4& v) {
    a.x = fmaf(s, v.x, a.x); a.y = fmaf(s, v.y, a.y);
    a.z = fmaf(s, v.z, a.z); a.w = fmaf(s, v.w, a.w);
}
__device__ __forceinline__ float fcomp(const float4& v, int k) {
    return k == 0 ? v.x : k == 1 ? v.y : k == 2 ? v.z : v.w;
}
__device__ __forceinline__ void red4(float4& a, int m) {
    a.x += __shfl_xor_sync(0xffffffffu, a.x, m);
    a.y += __shfl_xor_sync(0xffffffffu, a.y, m);
    a.z += __shfl_xor_sync(0xffffffffu, a.z, m);
    a.w += __shfl_xor_sync(0xffffffffu, a.w, m);
}

// K=256 half, 8 samples (row stride RS via __ldg), weights from smem.
// Thread = (kq in [0,8), q in [0,4)): k = j*32 + kq*4 (warp's kq-groups span ONE
// contiguous 128B line per sample-load). wcolp pre-offset to this thread's 4 cols;
// row stride 32 floats.
template<long RS>
__device__ __forceinline__ void gemm8(const float* __restrict__ src0,
                                      const float* __restrict__ wcolp,
                                      int kq, float4 acc[8]) {
    #pragma unroll 2
    for (int j = 0; j < 8; j++) {
        const int k = j * 32 + kq * 4;
        float4 av[8];
        #pragma unroll
        for (int s = 0; s < 8; s++)
            av[s] = __ldg((const float4*)(src0 + (long)s * RS + k));
        #pragma unroll
        for (int kk = 0; kk < 4; kk++) {
            float4 wv = *(const float4*)(wcolp + (k + kk) * 32);
            #pragma unroll
            for (int s = 0; s < 8; s++) fma4(acc[s], fcomp(av[s], kk), wv);
        }
    }
}

__global__ void __launch_bounds__(NT, 1)
enc_kernel(const float* __restrict__ x, const float* __restrict__ mask,
           const float* __restrict__ W_emb, const float* __restrict__ b_emb,
           const float* __restrict__ W, const float* __restrict__ U, const float* __restrict__ b,
           const float* __restrict__ W1, const float* __restrict__ b1,
           const float* __restrict__ Wa1, const float* __restrict__ Ua1, const float* __restrict__ ba1,
           const float* __restrict__ Wa3, const float* __restrict__ ba3,
           float* __restrict__ out)
{
    extern __shared__ float smem[];
    float* const wP     = smem;                  // [512][32]
    float* const wB1    = smem + OFF_WB1;        // [512][16]
    float* const sgb    = smem + OFF_SG;
    float* const sgx    = smem + OFF_SG + 64;
    float* const sgh    = smem + OFF_SG + 128;
    float* const swa3   = smem + OFF_WA3;
    float* const sb1    = smem + OFF_B1;
    float* const sbias1 = smem + OFF_BIAS1;

    const int tid = threadIdx.x, bid = blockIdx.x;
    const int w = tid >> 5, lane = tid & 31;
    const int kq = lane >> 2, q = lane & 3;      // 8-way K-split x 4 col-quads
    unsigned ep = g_gen;

    const int lvl1 = bid / 18, cb1 = (bid % 18) * 32;
    const bool p2on = bid < 112;
    const int lvl2 = bid >> 4, cb2 = (bid & 15) * 16;

    // phase-1 warp tile: 8 samples x 16 cols
    const int sg1 = w & 7, cg1 = w >> 3;
    const int ib1 = sg1 * 8;

    // ---- init dm + ring zero ----
    for (int idx = bid * NT + tid; idx < SS * BB; idx += NB * NT) {
        int t = idx >> 6, i = idx & 63;
        g_dm[idx] = mask[i * SS + t];
    }
    for (int idx = bid * NT + tid; idx < LEVELS * BB * HH; idx += NB * NT)
        r_xv[idx >> 14][3][idx & 16383] = 0.f;
    for (int idx = bid * NT + tid; idx < LEVELS * BB; idx += NB * NT)
        r_hv[idx >> 6][3][idx & 63] = 0.f;

    // ---- embedding (120 blocks: 8 col-slices x 15 t-groups) ----
    if (bid < 120) {
        const int esl = bid & 7, egr = bid >> 3;
        for (int idx = tid; idx < 256 * 32; idx += NT) {
            int k = idx >> 5, c = idx & 31;
            wP[idx] = W_emb[k * HH + esl * 32 + c];
        }
        __syncthreads();
        const float* wcolp = wP + cg1 * 16 + q * 4;
        for (int n = egr; n < SS; n += 15) {
            float4 acc[8];
            #pragma unroll
            for (int s = 0; s < 8; s++) acc[s] = make_float4(0.f, 0.f, 0.f, 0.f);
            gemm8<(long)SS * INF>(x + ((long)ib1 * SS + n) * INF, wcolp, kq, acc);
            #pragma unroll
            for (int s = 0; s < 8; s++) { red4(acc[s], 4); red4(acc[s], 8); red4(acc[s], 16); }
            if (lane < 4) {
                int col = esl * 32 + cg1 * 16 + lane * 4;
                float4 be = __ldg((const float4*)&b_emb[col]);
                #pragma unroll
                for (int s = 0; s < 8; s++) {
                    float4 o = acc[s];
                    o.x += be.x; o.y += be.y; o.z += be.z; o.w += be.w;
                    *(float4*)&g_xe[((long)n * BB + ib1 + s) * HH + col] = o;
                }
            }
        }
        __syncthreads();
    }

    // ---- stage persistent weights ----
    for (int idx = tid; idx < 512 * 32; idx += NT) {
        int k = idx >> 5, col = cb1 + (idx & 31);
        float v;
        if (col < 512) v = (k < 256) ? W[k * INNER + col] : U[(k - 256) * INNER + col];
        else { int a = col - 512; v = (k < 256) ? Wa1[k * AA + a] : Ua1[(k - 256) * AA + a]; }
        wP[idx] = v;
    }
    if (p2on) {
        for (int idx = tid; idx < 512 * 16; idx += NT)
            wB1[idx] = W1[(idx >> 4) * HH + cb2 + (idx & 15)];
        if (tid < 16) sb1[tid] = b1[cb2 + tid];
    }
    if (tid < 64) swa3[tid] = Wa3[tid];
    if (tid < 32) {
        int col = cb1 + tid;
        sbias1[tid] = (col < 512) ? b[col] : ba1[col - 512];
    }
    const float ba3v = __ldg(ba3);
    gbar(++ep);

    // ---- wavefront supersteps ----
    for (int u = 0; u < NSUPER; u++) {
        // ======== phase 1: [tmp|a] = lrelu([xt|h] @ [W;U|Wa1;Ua1] + bias) ========
        const int t1 = u - 2 * lvl1;
        if ((unsigned)t1 < SS) {
            const float* xt = (lvl1 == 0) ? &g_xe[(long)t1 * BB * HH]
                                          : r_xv[lvl1 - 1][t1 & 3];
            const float* hp = r_xv[lvl1][(t1 + 3) & 3];
            const float* wcolp = wP + cg1 * 16 + q * 4;
            float4 acc[8];
            #pragma unroll
            for (int s = 0; s < 8; s++) acc[s] = make_float4(0.f, 0.f, 0.f, 0.f);
            gemm8<HH>(xt + (long)ib1 * HH, wcolp,            kq, acc);
            gemm8<HH>(hp + (long)ib1 * HH, wcolp + 256 * 32, kq, acc);
            #pragma unroll
            for (int s = 0; s < 8; s++) { red4(acc[s], 4); red4(acc[s], 8); red4(acc[s], 16); }
            if (lane < 4) {
                const int col = cb1 + cg1 * 16 + lane * 4;
                float4 bv = *(const float4*)&sbias1[cg1 * 16 + lane * 4];
                #pragma unroll
                for (int s = 0; s < 8; s++) {
                    int i = ib1 + s;
                    float4 o;
                    o.x = lrelu(acc[s].x + bv.x); o.y = lrelu(acc[s].y + bv.y);
                    o.z = lrelu(acc[s].z + bv.z); o.w = lrelu(acc[s].w + bv.w);
                    if (col < 512) *(float4*)&g_tmpL[lvl1][i * INNER + col] = o;
                    else           *(float4*)&g_aL[lvl1][i * AA + col - 512] = o;
                }
            }
        }
        gbar(++ep);

        // ======== phase 2: gates + h = g(lrelu(tmp @ W1 + b1), xt, h_old) ========
        const int t2 = u - 2 * lvl2;
        if (p2on && (unsigned)t2 < SS) {
            {   // gate scalars: i = tid>>3, 8-lane dot split (overlaps with B GEMM below)
                int i = tid >> 3, qtr = tid & 7;
                const float* ar = &g_aL[lvl2][i * AA + qtr * 8];
                float p = 0.f;
                #pragma unroll
                for (int c = 0; c < 8; c += 4) {
                    float4 a4 = __ldg((const float4*)&ar[c]);
                    float4 w4 = *(const float4*)&swa3[qtr * 8 + c];
                    p += a4.x * w4.x + a4.y * w4.y + a4.z * w4.z + a4.w * w4.w;
                }
                p += __shfl_xor_sync(0xffffffffu, p, 1);
                p += __shfl_xor_sync(0xffffffffu, p, 2);
                p += __shfl_xor_sync(0xffffffffu, p, 4);
                if (qtr == 0) {
                    float sg  = 0.2f * (p + ba3v) + 0.5f;
                    float nmr = fminf(fmaxf(sg, 0.f), 1.f);
                    float lv  = (t2 == SS - 1) ? 1.f : 0.f;
                    float pm, ph;
                    if (lvl2 == 0) { pm = g_dm[t2 * BB + i]; ph = pm; }
                    else {
                        pm = (t2 == SS - 1) ? 1.f : r_nm[lvl2 - 1][(t2 + 1) & 3][i];
                        ph = r_hv[lvl2 - 1][t2 & 3][i];
                    }
                    float hvp = r_hv[lvl2][(t2 + 3) & 3][i];
                    float nm   = (1.f - lv) * (pm * ph * nmr);
                    float both = pm * ph * (1.f - nm) * hvp;
                    float xo   = pm * ph * (nm + (1.f - nm) * (1.f - hvp));
                    float ho   = (1.f - pm + pm * (1.f - ph)) * (1.f - nm) * hvp;
                    sgb[i] = both; sgx[i] = xo; sgh[i] = ho;
                    r_nm[lvl2][t2 & 3][i] = nm;
                    r_hv[lvl2][t2 & 3][i] = both + xo + ho;
                }
            }
            // B GEMM: K=512, 16 cols; warp = 4 samples x 16 cols, k = j*32 + kq*4
            const float* tl = g_tmpL[lvl2];
            const int ib = 4 * w;
            float4 acc[4];
            #pragma unroll
            for (int s = 0; s < 4; s++) acc[s] = make_float4(0.f, 0.f, 0.f, 0.f);
            #pragma unroll 2
            for (int j = 0; j < 16; j++) {
                const int k = j * 32 + kq * 4;
                float4 tv[4];
                #pragma unroll
                for (int s = 0; s < 4; s++)
                    tv[s] = __ldg((const float4*)(tl + (long)(ib + s) * INNER + k));
                #pragma unroll
                for (int kk = 0; kk < 4; kk++) {
                    float4 wv = *(const float4*)&wB1[(k + kk) * 16 + q * 4];
                    #pragma unroll
                    for (int s = 0; s < 4; s++) fma4(acc[s], fcomp(tv[s], kk), wv);
                }
            }
            #pragma unroll
            for (int s = 0; s < 4; s++) { red4(acc[s], 4); red4(acc[s], 8); red4(acc[s], 16); }
            __syncthreads();                    // gates now visible
            if (lane < 4) {
                const int col = cb2 + lane * 4;
                float4 b1v = *(const float4*)&sb1[lane * 4];
                const float* xtp = (lvl2 == 0) ? &g_xe[(long)t2 * BB * HH]
                                               : r_xv[lvl2 - 1][t2 & 3];
                const float* hop = r_xv[lvl2][(t2 + 3) & 3];
                float* hnp = r_xv[lvl2][t2 & 3];
                #pragma unroll
                for (int s = 0; s < 4; s++) {
                    int i = ib + s;
                    float h0 = lrelu(acc[s].x + b1v.x);
                    float h1 = lrelu(acc[s].y + b1v.y);
                    float h2 = lrelu(acc[s].z + b1v.z);
                    float h3 = lrelu(acc[s].w + b1v.w);
                    float bo = sgb[i], xo = sgx[i], ho = sgh[i];
                    float4 xt4 = __ldg((const float4*)&xtp[i * HH + col]);
                    float4 hl4 = __ldg((const float4*)&hop[i * HH + col]);
                    float4 hn;
                    hn.x = bo * h0 + xo * xt4.x + ho * hl4.x;
                    hn.y = bo * h1 + xo * xt4.y + ho * hl4.y;
                    hn.z = bo * h2 + xo * xt4.z + ho * hl4.z;
                    hn.w = bo * h3 + xo * xt4.w + ho * hl4.w;
                    *(float4*)&hnp[i * HH + col] = hn;
                    if (lvl2 == LEVELS - 1 && t2 == SS - 1)
                        *(float4*)&out[i * HH + col] = hn;
                }
            }
        }
        gbar(++ep);
    }
}

extern "C" void kernel_launch(void* const* d_in, const int* in_sizes, int n_in,
                              void* d_out, int out_size) {
    const float* x     = (const float*)d_in[0];
    const float* mask  = (const float*)d_in[1];
    const float* W_emb = (const float*)d_in[3];
    const float* b_emb = (const float*)d_in[4];
    const float* W     = (const float*)d_in[5];
    const float* U     = (const float*)d_in[6];
    const float* b     = (const float*)d_in[7];
    const float* W1    = (const float*)d_in[8];
    const float* b1    = (const float*)d_in[9];
    const float* Wa1   = (const float*)d_in[10];
    const float* Ua1   = (const float*)d_in[11];
    const float* ba1   = (const float*)d_in[12];
    const float* Wa3   = (const float*)d_in[13];
    const float* ba3   = (const float*)d_in[14];
    float* out = (float*)d_out;

    cudaFuncSetAttribute(enc_kernel, cudaFuncAttributeMaxDynamicSharedMemorySize, SMEM_BYTES);
    enc_kernel<<<NB, NT, SMEM_BYTES>>>(x, mask, W_emb, b_emb, W, U, b, W1, b1,
                                       Wa1, Ua1, ba1, Wa3, ba3, out);
}

// round 13
// speedup vs baseline: 1.1709x; 1.0677x over previous
#include <cuda_runtime.h>

#define SS     256
#define BB     64
#define INF    256
#define HH     256
#define INNER  512
#define AA     64
#define LEVELS 7
#define NB     126
#define NT     512
#define NSUPER (SS + 2 * (LEVELS - 1))   // 268

// smem (floats): wP[512][32] permuted @0 ; wB1[512][16] permuted @16384 ;
// gates 3*64 @24576 ; swa3[64] @24768 ; sb1[16] @24832 ; sbias1[32] @24848
#define OFF_WB1   16384
#define OFF_SG    24576
#define OFF_WA3   24768
#define OFF_B1    24832
#define OFF_BIAS1 24848
#define SMEM_FLOATS 24896
#define SMEM_BYTES  (SMEM_FLOATS * 4)

__device__ float g_xe[SS * BB * HH];
__device__ float g_dm[SS * BB];
__device__ float g_tmpL[LEVELS][BB * INNER];
__device__ float g_aL[LEVELS][BB * AA];
__device__ float r_xv[LEVELS][4][BB * HH];
__device__ float r_nm[LEVELS][4][BB];
__device__ float r_hv[LEVELS][4][BB];

__device__ volatile unsigned g_arrive[NB];
__device__ volatile unsigned g_gen = 0;

__device__ __forceinline__ void gbar(unsigned ep) {
    __syncthreads();
    if (blockIdx.x == 0) {
        int tid = threadIdx.x;
        if (tid >= 1 && tid < NB) {
            while (g_arrive[tid] < ep) { }
        }
        __syncthreads();
        if (tid == 0) { __threadfence(); g_gen = ep; }
        __syncthreads();
    } else {
        if (threadIdx.x == 0) {
            __threadfence();                 // release
            g_arrive[blockIdx.x] = ep;
            while (g_gen < ep) { }
            __threadfence();                 // acquire
        }
        __syncthreads();
    }
}

__device__ __forceinline__ float lrelu(float z) { return z >= 0.f ? z : 0.01f * z; }

__device__ __forceinline__ void fma4(float4& a, float s, const float4& v) {
    a.x = fmaf(s, v.x, a.x); a.y = fmaf(s, v.y, a.y);
    a.z = fmaf(s, v.z, a.z); a.w = fmaf(s, v.w, a.w);
}
__device__ __forceinline__ float fcomp(const float4& v, int k) {
    return k == 0 ? v.x : k == 1 ? v.y : k == 2 ? v.z : v.w;
}
__device__ __forceinline__ void red4(float4& a, int m) {
    a.x += __shfl_xor_sync(0xffffffffu, a.x, m);
    a.y += __shfl_xor_sync(0xffffffffu, a.y, m);
    a.z += __shfl_xor_sync(0xffffffffu, a.z, m);
    a.w += __shfl_xor_sync(0xffffffffu, a.w, m);
}

// Permuted index for wP (32 cols): k=j*32+kq*4+kk, cc=cg*16+q*4+c
// float idx = (((j*4+kk)*2+cg)*32 + kq*4 + q)*4 + c  -> warp reads 512B contiguous
__device__ __forceinline__ int permP(int k, int cc) {
    int j = k >> 5, kq = (k >> 2) & 7, kk = k & 3;
    int cg = cc >> 4, q = (cc >> 2) & 3, c = cc & 3;
    return ((((j * 4 + kk) * 2 + cg) * 32) + kq * 4 + q) * 4 + c;
}
// Permuted index for wB1 (16 cols): float idx = (((j*4+kk)*8+kq)*4+q)*4+c
__device__ __forceinline__ int permB(int k, int cc) {
    int j = k >> 5, kq = (k >> 2) & 7, kk = k & 3;
    int q = cc >> 2, c = cc & 3;
    return (((j * 4 + kk) * 8 + kq) * 4 + q) * 4 + c;
}

// K=256 half, 8 samples (row stride RS via __ldg), permuted smem weights.
// wb4 pre-offset = wP4 + cg*32 + kq*4 + q (+2048 for second half); stride 64/ (j,kk).
template<long RS>
__device__ __forceinline__ void gemm8(const float* __restrict__ src0,
                                      const float4* __restrict__ wb4,
                                      int kq, float4 acc[8]) {
    #pragma unroll 2
    for (int j = 0; j < 8; j++) {
        const int k = j * 32 + kq * 4;
        float4 av[8];
        #pragma unroll
        for (int s = 0; s < 8; s++)
            av[s] = __ldg((const float4*)(src0 + (long)s * RS + k));
        #pragma unroll
        for (int kk = 0; kk < 4; kk++) {
            float4 wv = wb4[(j * 4 + kk) * 64];
            #pragma unroll
            for (int s = 0; s < 8; s++) fma4(acc[s], fcomp(av[s], kk), wv);
        }
    }
}

__global__ void __launch_bounds__(NT, 1)
enc_kernel(const float* __restrict__ x, const float* __restrict__ mask,
           const float* __restrict__ W_emb, const float* __restrict__ b_emb,
           const float* __restrict__ W, const float* __restrict__ U, const float* __restrict__ b,
           const float* __restrict__ W1, const float* __restrict__ b1,
           const float* __restrict__ Wa1, const float* __restrict__ Ua1, const float* __restrict__ ba1,
           const float* __restrict__ Wa3, const float* __restrict__ ba3,
           float* __restrict__ out)
{
    extern __shared__ float smem[];
    float* const wP     = smem;                  // [512][32] permuted
    float* const wB1    = smem + OFF_WB1;        // [512][16] permuted
    float* const sgb    = smem + OFF_SG;
    float* const sgx    = smem + OFF_SG + 64;
    float* const sgh    = smem + OFF_SG + 128;
    float* const swa3   = smem + OFF_WA3;
    float* const sb1    = smem + OFF_B1;
    float* const sbias1 = smem + OFF_BIAS1;

    const int tid = threadIdx.x, bid = blockIdx.x;
    const int w = tid >> 5, lane = tid & 31;
    const int kq = lane >> 2, q = lane & 3;      // 8-way K-split x 4 col-quads
    unsigned ep = g_gen;

    const int lvl1 = bid / 18, cb1 = (bid % 18) * 32;
    const bool p2on = bid < 112;
    const int lvl2 = bid >> 4, cb2 = (bid & 15) * 16;

    // phase-1 warp tile: 8 samples x 16 cols
    const int sg1 = w & 7, cg1 = w >> 3;
    const int ib1 = sg1 * 8;

    // ---- init dm + ring zero ----
    for (int idx = bid * NT + tid; idx < SS * BB; idx += NB * NT) {
        int t = idx >> 6, i = idx & 63;
        g_dm[idx] = mask[i * SS + t];
    }
    for (int idx = bid * NT + tid; idx < LEVELS * BB * HH; idx += NB * NT)
        r_xv[idx >> 14][3][idx & 16383] = 0.f;
    for (int idx = bid * NT + tid; idx < LEVELS * BB; idx += NB * NT)
        r_hv[idx >> 6][3][idx & 63] = 0.f;

    // ---- embedding (120 blocks: 8 col-slices x 15 t-groups) ----
    if (bid < 120) {
        const int esl = bid & 7, egr = bid >> 3;
        for (int idx = tid; idx < 256 * 32; idx += NT) {
            int k = idx >> 5, cc = idx & 31;
            wP[permP(k, cc)] = W_emb[k * HH + esl * 32 + cc];
        }
        __syncthreads();
        const float4* wb4 = (const float4*)wP + cg1 * 32 + kq * 4 + q;
        for (int n = egr; n < SS; n += 15) {
            float4 acc[8];
            #pragma unroll
            for (int s = 0; s < 8; s++) acc[s] = make_float4(0.f, 0.f, 0.f, 0.f);
            gemm8<(long)SS * INF>(x + ((long)ib1 * SS + n) * INF, wb4, kq, acc);
            #pragma unroll
            for (int s = 0; s < 8; s++) { red4(acc[s], 4); red4(acc[s], 8); red4(acc[s], 16); }
            if (lane < 4) {
                int col = esl * 32 + cg1 * 16 + lane * 4;
                float4 be = __ldg((const float4*)&b_emb[col]);
                #pragma unroll
                for (int s = 0; s < 8; s++) {
                    float4 o = acc[s];
                    o.x += be.x; o.y += be.y; o.z += be.z; o.w += be.w;
                    *(float4*)&g_xe[((long)n * BB + ib1 + s) * HH + col] = o;
                }
            }
        }
        __syncthreads();
    }

    // ---- stage persistent weights (permuted) ----
    for (int idx = tid; idx < 512 * 32; idx += NT) {
        int k = idx >> 5, cc = idx & 31, col = cb1 + cc;
        float v;
        if (col < 512) v = (k < 256) ? W[k * INNER + col] : U[(k - 256) * INNER + col];
        else { int a = col - 512; v = (k < 256) ? Wa1[k * AA + a] : Ua1[(k - 256) * AA + a]; }
        wP[permP(k & 255, cc) + (k >> 8) * 8192] = v;
    }
    if (p2on) {
        for (int idx = tid; idx < 512 * 16; idx += NT) {
            int k = idx >> 4, cc = idx & 15;
            wB1[permB(k, cc)] = W1[k * HH + cb2 + cc];
        }
        if (tid < 16) sb1[tid] = b1[cb2 + tid];
    }
    if (tid < 64) swa3[tid] = Wa3[tid];
    if (tid < 32) {
        int col = cb1 + tid;
        sbias1[tid] = (col < 512) ? b[col] : ba1[col - 512];
    }
    const float ba3v = __ldg(ba3);
    gbar(++ep);

    // ---- wavefront supersteps ----
    for (int u = 0; u < NSUPER; u++) {
        // ======== phase 1: [tmp|a] = lrelu([xt|h] @ [W;U|Wa1;Ua1] + bias) ========
        const int t1 = u - 2 * lvl1;
        if ((unsigned)t1 < SS) {
            const float* xt = (lvl1 == 0) ? &g_xe[(long)t1 * BB * HH]
                                          : r_xv[lvl1 - 1][t1 & 3];
            const float* hp = r_xv[lvl1][(t1 + 3) & 3];
            const float4* wb4 = (const float4*)wP + cg1 * 32 + kq * 4 + q;
            float4 acc[8];
            #pragma unroll
            for (int s = 0; s < 8; s++) acc[s] = make_float4(0.f, 0.f, 0.f, 0.f);
            gemm8<HH>(xt + (long)ib1 * HH, wb4,        kq, acc);
            gemm8<HH>(hp + (long)ib1 * HH, wb4 + 2048, kq, acc);
            #pragma unroll
            for (int s = 0; s < 8; s++) { red4(acc[s], 4); red4(acc[s], 8); red4(acc[s], 16); }
            if (lane < 4) {
                const int col = cb1 + cg1 * 16 + lane * 4;
                float4 bv = *(const float4*)&sbias1[cg1 * 16 + lane * 4];
                #pragma unroll
                for (int s = 0; s < 8; s++) {
                    int i = ib1 + s;
                    float4 o;
                    o.x = lrelu(acc[s].x + bv.x); o.y = lrelu(acc[s].y + bv.y);
                    o.z = lrelu(acc[s].z + bv.z); o.w = lrelu(acc[s].w + bv.w);
                    if (col < 512) *(float4*)&g_tmpL[lvl1][i * INNER + col] = o;
                    else           *(float4*)&g_aL[lvl1][i * AA + col - 512] = o;
                }
            }
        }
        gbar(++ep);

        // ======== phase 2: gates + h = g(lrelu(tmp @ W1 + b1), xt, h_old) ========
        const int t2 = u - 2 * lvl2;
        if (p2on && (unsigned)t2 < SS) {
            {   // gate scalars: i = tid>>3, 8-lane dot split
                int i = tid >> 3, qtr = tid & 7;
                const float* ar = &g_aL[lvl2][i * AA + qtr * 8];
                float p = 0.f;
                #pragma unroll
                for (int c = 0; c < 8; c += 4) {
                    float4 a4 = __ldg((const float4*)&ar[c]);
                    float4 w4 = *(const float4*)&swa3[qtr * 8 + c];
                    p += a4.x * w4.x + a4.y * w4.y + a4.z * w4.z + a4.w * w4.w;
                }
                p += __shfl_xor_sync(0xffffffffu, p, 1);
                p += __shfl_xor_sync(0xffffffffu, p, 2);
                p += __shfl_xor_sync(0xffffffffu, p, 4);
                if (qtr == 0) {
                    float sg  = 0.2f * (p + ba3v) + 0.5f;
                    float nmr = fminf(fmaxf(sg, 0.f), 1.f);
                    float lv  = (t2 == SS - 1) ? 1.f : 0.f;
                    float pm, ph;
                    if (lvl2 == 0) { pm = g_dm[t2 * BB + i]; ph = pm; }
                    else {
                        pm = (t2 == SS - 1) ? 1.f : r_nm[lvl2 - 1][(t2 + 1) & 3][i];
                        ph = r_hv[lvl2 - 1][t2 & 3][i];
                    }
                    float hvp = r_hv[lvl2][(t2 + 3) & 3][i];
                    float nm   = (1.f - lv) * (pm * ph * nmr);
                    float both = pm * ph * (1.f - nm) * hvp;
                    float xo   = pm * ph * (nm + (1.f - nm) * (1.f - hvp));
                    float ho   = (1.f - pm + pm * (1.f - ph)) * (1.f - nm) * hvp;
                    sgb[i] = both; sgx[i] = xo; sgh[i] = ho;
                    r_nm[lvl2][t2 & 3][i] = nm;
                    r_hv[lvl2][t2 & 3][i] = both + xo + ho;
                }
            }
            // B GEMM: K=512, 16 cols; warp = 4 samples x 16 cols, permuted weights
            const float* tl = g_tmpL[lvl2];
            const int ib = 4 * w;
            const float4* wb4 = (const float4*)wB1 + kq * 4 + q;
            float4 acc[4];
            #pragma unroll
            for (int s = 0; s < 4; s++) acc[s] = make_float4(0.f, 0.f, 0.f, 0.f);
            #pragma unroll 2
            for (int j = 0; j < 16; j++) {
                const int k = j * 32 + kq * 4;
                float4 tv[4];
                #pragma unroll
                for (int s = 0; s < 4; s++)
                    tv[s] = __ldg((const float4*)(tl + (long)(ib + s) * INNER + k));
                #pragma unroll
                for (int kk = 0; kk < 4; kk++) {
                    float4 wv = wb4[(j * 4 + kk) * 32];
                    #pragma unroll
                    for (int s = 0; s < 4; s++) fma4(acc[s], fcomp(tv[s], kk), wv);
                }
            }
            #pragma unroll
            for (int s = 0; s < 4; s++) { red4(acc[s], 4); red4(acc[s], 8); red4(acc[s], 16); }
            __syncthreads();                    // gates now visible
            if (lane < 4) {
                const int col = cb2 + lane * 4;
                float4 b1v = *(const float4*)&sb1[lane * 4];
                const float* xtp = (lvl2 == 0) ? &g_xe[(long)t2 * BB * HH]
                                               : r_xv[lvl2 - 1][t2 & 3];
                const float* hop = r_xv[lvl2][(t2 + 3) & 3];
                float* hnp = r_xv[lvl2][t2 & 3];
                #pragma unroll
                for (int s = 0; s < 4; s++) {
                    int i = ib + s;
                    float h0 = lrelu(acc[s].x + b1v.x);
                    float h1 = lrelu(acc[s].y + b1v.y);
                    float h2 = lrelu(acc[s].z + b1v.z);
                    float h3 = lrelu(acc[s].w + b1v.w);
                    float bo = sgb[i], xo = sgx[i], ho = sgh[i];
                    float4 xt4 = __ldg((const float4*)&xtp[i * HH + col]);
                    float4 hl4 = __ldg((const float4*)&hop[i * HH + col]);
                    float4 hn;
                    hn.x = bo * h0 + xo * xt4.x + ho * hl4.x;
                    hn.y = bo * h1 + xo * xt4.y + ho * hl4.y;
                    hn.z = bo * h2 + xo * xt4.z + ho * hl4.z;
                    hn.w = bo * h3 + xo * xt4.w + ho * hl4.w;
                    *(float4*)&hnp[i * HH + col] = hn;
                    if (lvl2 == LEVELS - 1 && t2 == SS - 1)
                        *(float4*)&out[i * HH + col] = hn;
                }
            }
        }
        gbar(++ep);
    }
}

extern "C" void kernel_launch(void* const* d_in, const int* in_sizes, int n_in,
                              void* d_out, int out_size) {
    const float* x     = (const float*)d_in[0];
    const float* mask  = (const float*)d_in[1];
    const float* W_emb = (const float*)d_in[3];
    const float* b_emb = (const float*)d_in[4];
    const float* W     = (const float*)d_in[5];
    const float* U     = (const float*)d_in[6];
    const float* b     = (const float*)d_in[7];
    const float* W1    = (const float*)d_in[8];
    const float* b1    = (const float*)d_in[9];
    const float* Wa1   = (const float*)d_in[10];
    const float* Ua1   = (const float*)d_in[11];
    const float* ba1   = (const float*)d_in[12];
    const float* Wa3   = (const float*)d_in[13];
    const float* ba3   = (const float*)d_in[14];
    float* out = (float*)d_out;

    cudaFuncSetAttribute(enc_kernel, cudaFuncAttributeMaxDynamicSharedMemorySize, SMEM_BYTES);
    enc_kernel<<<NB, NT, SMEM_BYTES>>>(x, mask, W_emb, b_emb, W, U, b, W1, b1,
                                       Wa1, Ua1, ba1, Wa3, ba3, out);
}

// round 14
// speedup vs baseline: 1.3427x; 1.1468x over previous
#include <cuda_runtime.h>

#define SS     256
#define BB     64
#define INF    256
#define HH     256
#define INNER  512
#define AA     64
#define LEVELS 7
#define NB     126
#define NT     512
#define NSUPER (SS + 2 * (LEVELS - 1))   // 268

#define OFF_WB1   16384
#define OFF_SG    24576
#define OFF_WA3   24768
#define OFF_B1    24832
#define OFF_BIAS1 24848
#define SMEM_FLOATS 24896
#define SMEM_BYTES  (SMEM_FLOATS * 4)

__device__ float g_xe[SS * BB * HH];
__device__ float g_dm[SS * BB];
__device__ float g_tmpL[LEVELS][BB * INNER];
__device__ float g_aL[LEVELS][BB * AA];
__device__ float r_xv[LEVELS][4][BB * HH];
__device__ float r_nm[LEVELS][4][BB];
__device__ float r_hv[LEVELS][4][BB];

// dataflow counters: cnt1[l] += 1 per phase1-slice (18/t), cnt2[l] += 1 per phase2-slice (16/t)
__device__ unsigned cnt1[LEVELS];
__device__ unsigned cnt2[LEVELS];

__device__ volatile unsigned g_arrive[NB];
__device__ volatile unsigned g_gen = 0;

__device__ __forceinline__ void gbar(unsigned ep) {
    __syncthreads();
    if (blockIdx.x == 0) {
        int tid = threadIdx.x;
        if (tid >= 1 && tid < NB) {
            while (g_arrive[tid] < ep) { }
        }
        __syncthreads();
        if (tid == 0) { __threadfence(); g_gen = ep; }
        __syncthreads();
    } else {
        if (threadIdx.x == 0) {
            __threadfence();
            g_arrive[blockIdx.x] = ep;
            while (g_gen < ep) { }
            __threadfence();
        }
        __syncthreads();
    }
}

__device__ __forceinline__ float lrelu(float z) { return z >= 0.f ? z : 0.01f * z; }

__device__ __forceinline__ void fma4(float4& a, float s, const float4& v) {
    a.x = fmaf(s, v.x, a.x); a.y = fmaf(s, v.y, a.y);
    a.z = fmaf(s, v.z, a.z); a.w = fmaf(s, v.w, a.w);
}
__device__ __forceinline__ float fcomp(const float4& v, int k) {
    return k == 0 ? v.x : k == 1 ? v.y : k == 2 ? v.z : v.w;
}
__device__ __forceinline__ void red4(float4& a, int m) {
    a.x += __shfl_xor_sync(0xffffffffu, a.x, m);
    a.y += __shfl_xor_sync(0xffffffffu, a.y, m);
    a.z += __shfl_xor_sync(0xffffffffu, a.z, m);
    a.w += __shfl_xor_sync(0xffffffffu, a.w, m);
}

// Permuted smem weight layouts (conflict-free; warp reads 512B contiguous per (j,kk))
__device__ __forceinline__ int permP(int k, int cc) {
    int j = k >> 5, kq = (k >> 2) & 7, kk = k & 3;
    int cg = cc >> 4, q = (cc >> 2) & 3, c = cc & 3;
    return ((((j * 4 + kk) * 2 + cg) * 32) + kq * 4 + q) * 4 + c;
}
__device__ __forceinline__ int permB(int k, int cc) {
    int j = k >> 5, kq = (k >> 2) & 7, kk = k & 3;
    int q = cc >> 2, c = cc & 3;
    return (((j * 4 + kk) * 8 + kq) * 4 + q) * 4 + c;
}

// K=256 half, 8 samples via __ldcg (L2-coherent), permuted smem weights.
template<long RS>
__device__ __forceinline__ void gemm8(const float* __restrict__ src0,
                                      const float4* __restrict__ wb4,
                                      int kq, float4 acc[8]) {
    #pragma unroll 2
    for (int j = 0; j < 8; j++) {
        const int k = j * 32 + kq * 4;
        float4 av[8];
        #pragma unroll
        for (int s = 0; s < 8; s++)
            av[s] = __ldcg((const float4*)(src0 + (long)s * RS + k));
        #pragma unroll
        for (int kk = 0; kk < 4; kk++) {
            float4 wv = wb4[(j * 4 + kk) * 64];
            #pragma unroll
            for (int s = 0; s < 8; s++) fma4(acc[s], fcomp(av[s], kk), wv);
        }
    }
}

__global__ void __launch_bounds__(NT, 1)
enc_kernel(const float* __restrict__ x, const float* __restrict__ mask,
           const float* __restrict__ W_emb, const float* __restrict__ b_emb,
           const float* __restrict__ W, const float* __restrict__ U, const float* __restrict__ b,
           const float* __restrict__ W1, const float* __restrict__ b1,
           const float* __restrict__ Wa1, const float* __restrict__ Ua1, const float* __restrict__ ba1,
           const float* __restrict__ Wa3, const float* __restrict__ ba3,
           float* __restrict__ out)
{
    extern __shared__ float smem[];
    float* const wP     = smem;                  // [512][32] permuted
    float* const wB1    = smem + OFF_WB1;        // [512][16] permuted
    float* const sgb    = smem + OFF_SG;
    float* const sgx    = smem + OFF_SG + 64;
    float* const sgh    = smem + OFF_SG + 128;
    float* const swa3   = smem + OFF_WA3;
    float* const sb1    = smem + OFF_B1;
    float* const sbias1 = smem + OFF_BIAS1;

    const int tid = threadIdx.x, bid = blockIdx.x;
    const int w = tid >> 5, lane = tid & 31;
    const int kq = lane >> 2, q = lane & 3;
    unsigned ep = g_gen;

    const int lvl1 = bid / 18, cb1 = (bid % 18) * 32;
    const bool p2on = bid < 112;
    const int lvl2 = bid >> 4, cb2 = (bid & 15) * 16;

    const int sg1 = w & 7, cg1 = w >> 3;
    const int ib1 = sg1 * 8;

    // ---- init dm + ring zero + counters ----
    for (int idx = bid * NT + tid; idx < SS * BB; idx += NB * NT) {
        int t = idx >> 6, i = idx & 63;
        g_dm[idx] = mask[i * SS + t];
    }
    for (int idx = bid * NT + tid; idx < LEVELS * BB * HH; idx += NB * NT)
        r_xv[idx >> 14][3][idx & 16383] = 0.f;
    for (int idx = bid * NT + tid; idx < LEVELS * BB; idx += NB * NT)
        r_hv[idx >> 6][3][idx & 63] = 0.f;
    if (bid == NB - 1 && tid < LEVELS) { cnt1[tid] = 0; cnt2[tid] = 0; }

    // ---- embedding (120 blocks: 8 col-slices x 15 t-groups) ----
    if (bid < 120) {
        const int esl = bid & 7, egr = bid >> 3;
        for (int idx = tid; idx < 256 * 32; idx += NT) {
            int k = idx >> 5, cc = idx & 31;
            wP[permP(k, cc)] = W_emb[k * HH + esl * 32 + cc];
        }
        __syncthreads();
        const float4* wb4 = (const float4*)wP + cg1 * 32 + kq * 4 + q;
        for (int n = egr; n < SS; n += 15) {
            float4 acc[8];
            #pragma unroll
            for (int s = 0; s < 8; s++) acc[s] = make_float4(0.f, 0.f, 0.f, 0.f);
            gemm8<(long)SS * INF>(x + ((long)ib1 * SS + n) * INF, wb4, kq, acc);
            #pragma unroll
            for (int s = 0; s < 8; s++) { red4(acc[s], 4); red4(acc[s], 8); red4(acc[s], 16); }
            if (lane < 4) {
                int col = esl * 32 + cg1 * 16 + lane * 4;
                float4 be = __ldg((const float4*)&b_emb[col]);
                #pragma unroll
                for (int s = 0; s < 8; s++) {
                    float4 o = acc[s];
                    o.x += be.x; o.y += be.y; o.z += be.z; o.w += be.w;
                    *(float4*)&g_xe[((long)n * BB + ib1 + s) * HH + col] = o;
                }
            }
        }
        __syncthreads();
    }

    // ---- stage persistent weights (permuted) ----
    for (int idx = tid; idx < 512 * 32; idx += NT) {
        int k = idx >> 5, cc = idx & 31, col = cb1 + cc;
        float v;
        if (col < 512) v = (k < 256) ? W[k * INNER + col] : U[(k - 256) * INNER + col];
        else { int a = col - 512; v = (k < 256) ? Wa1[k * AA + a] : Ua1[(k - 256) * AA + a]; }
        wP[permP(k & 255, cc) + (k >> 8) * 8192] = v;
    }
    if (p2on) {
        for (int idx = tid; idx < 512 * 16; idx += NT) {
            int k = idx >> 4, cc = idx & 15;
            wB1[permB(k, cc)] = W1[k * HH + cb2 + cc];
        }
        if (tid < 16) sb1[tid] = b1[cb2 + tid];
    }
    if (tid < 64) swa3[tid] = Wa3[tid];
    if (tid < 32) {
        int col = cb1 + tid;
        sbias1[tid] = (col < 512) ? b[col] : ba1[col - 512];
    }
    const float ba3v = __ldg(ba3);
    gbar(++ep);

    // ---- wavefront supersteps (dataflow-synced; no global barrier) ----
    for (int u = 0; u < NSUPER; u++) {
        // ======== phase 1: [tmp|a] = lrelu([xt|h] @ [W;U|Wa1;Ua1] + bias) ========
        const int t1 = u - 2 * lvl1;
        if ((unsigned)t1 < SS) {
            // wait: h(lvl1,t1-1) [cnt2[lvl1] >= 16*t1, also tmp WAR] ;
            //       xt = h(lvl1-1,t1) [cnt2[lvl1-1] >= 16*(t1+1)]
            if (tid == 0) {
                const int w1 = 16 * t1, w2 = 16 * (t1 + 1);
                for (;;) {
                    unsigned a = *(volatile unsigned*)&cnt2[lvl1];
                    unsigned bv = (lvl1 > 0) ? *(volatile unsigned*)&cnt2[lvl1 - 1] : 0u;
                    if ((int)a >= w1 && (lvl1 == 0 || (int)bv >= w2)) break;
                }
            }
            __syncthreads();

            const float* xt = (lvl1 == 0) ? &g_xe[(long)t1 * BB * HH]
                                          : r_xv[lvl1 - 1][t1 & 3];
            const float* hp = r_xv[lvl1][(t1 + 3) & 3];
            const float4* wb4 = (const float4*)wP + cg1 * 32 + kq * 4 + q;
            float4 acc[8];
            #pragma unroll
            for (int s = 0; s < 8; s++) acc[s] = make_float4(0.f, 0.f, 0.f, 0.f);
            gemm8<HH>(xt + (long)ib1 * HH, wb4,        kq, acc);
            gemm8<HH>(hp + (long)ib1 * HH, wb4 + 2048, kq, acc);
            #pragma unroll
            for (int s = 0; s < 8; s++) { red4(acc[s], 4); red4(acc[s], 8); red4(acc[s], 16); }
            if (lane < 4) {
                const int col = cb1 + cg1 * 16 + lane * 4;
                float4 bv = *(const float4*)&sbias1[cg1 * 16 + lane * 4];
                #pragma unroll
                for (int s = 0; s < 8; s++) {
                    int i = ib1 + s;
                    float4 o;
                    o.x = lrelu(acc[s].x + bv.x); o.y = lrelu(acc[s].y + bv.y);
                    o.z = lrelu(acc[s].z + bv.z); o.w = lrelu(acc[s].w + bv.w);
                    if (col < 512) *(float4*)&g_tmpL[lvl1][i * INNER + col] = o;
                    else           *(float4*)&g_aL[lvl1][i * AA + col - 512] = o;
                }
            }
            __syncthreads();
            if (tid == 0) { __threadfence(); atomicAdd(&cnt1[lvl1], 1u); }
        }

        // ======== phase 2: gates + h = g(lrelu(tmp @ W1 + b1), xt, h_old) ========
        const int t2 = u - 2 * lvl2;
        if (p2on && (unsigned)t2 < SS) {
            // wait: tmp(lvl2,t2) ready ; gates deps from lvl2-1 ; ring-WAR vs lvl2+1
            if (tid == 0) {
                const int wA = 18 * (t2 + 1);
                const int wB = 16 * ((t2 + 2 > 256) ? 256 : (t2 + 2));
                const int wC = 18 * (t2 - 3);
                const int wD = 16 * (t2 - 3);
                for (;;) {
                    unsigned a = *(volatile unsigned*)&cnt1[lvl2];
                    unsigned bv = (lvl2 > 0) ? *(volatile unsigned*)&cnt2[lvl2 - 1] : 0u;
                    unsigned c = (lvl2 < 6) ? *(volatile unsigned*)&cnt1[lvl2 + 1] : 0u;
                    unsigned d = (lvl2 < 6) ? *(volatile unsigned*)&cnt2[lvl2 + 1] : 0u;
                    bool ok = ((int)a >= wA)
                           && (lvl2 == 0 || (int)bv >= wB)
                           && (lvl2 == 6 || ((int)c >= wC && (int)d >= wD));
                    if (ok) break;
                }
            }
            __syncthreads();

            {   // gate scalars: i = tid>>3, 8-lane dot split
                int i = tid >> 3, qtr = tid & 7;
                const float* ar = &g_aL[lvl2][i * AA + qtr * 8];
                float p = 0.f;
                #pragma unroll
                for (int c = 0; c < 8; c += 4) {
                    float4 a4 = __ldcg((const float4*)&ar[c]);
                    float4 w4 = *(const float4*)&swa3[qtr * 8 + c];
                    p += a4.x * w4.x + a4.y * w4.y + a4.z * w4.z + a4.w * w4.w;
                }
                p += __shfl_xor_sync(0xffffffffu, p, 1);
                p += __shfl_xor_sync(0xffffffffu, p, 2);
                p += __shfl_xor_sync(0xffffffffu, p, 4);
                if (qtr == 0) {
                    float sg  = 0.2f * (p + ba3v) + 0.5f;
                    float nmr = fminf(fmaxf(sg, 0.f), 1.f);
                    float lv  = (t2 == SS - 1) ? 1.f : 0.f;
                    float pm, ph;
                    if (lvl2 == 0) { pm = g_dm[t2 * BB + i]; ph = pm; }
                    else {
                        pm = (t2 == SS - 1) ? 1.f : __ldcg(&r_nm[lvl2 - 1][(t2 + 1) & 3][i]);
                        ph = __ldcg(&r_hv[lvl2 - 1][t2 & 3][i]);
                    }
                    float hvp = __ldcg(&r_hv[lvl2][(t2 + 3) & 3][i]);
                    float nm   = (1.f - lv) * (pm * ph * nmr);
                    float both = pm * ph * (1.f - nm) * hvp;
                    float xo   = pm * ph * (nm + (1.f - nm) * (1.f - hvp));
                    float ho   = (1.f - pm + pm * (1.f - ph)) * (1.f - nm) * hvp;
                    sgb[i] = both; sgx[i] = xo; sgh[i] = ho;
                    r_nm[lvl2][t2 & 3][i] = nm;
                    r_hv[lvl2][t2 & 3][i] = both + xo + ho;
                }
            }
            // B GEMM: K=512, 16 cols; warp = 4 samples x 16 cols, permuted weights
            const float* tl = g_tmpL[lvl2];
            const int ib = 4 * w;
            const float4* wb4 = (const float4*)wB1 + kq * 4 + q;
            float4 acc[4];
            #pragma unroll
            for (int s = 0; s < 4; s++) acc[s] = make_float4(0.f, 0.f, 0.f, 0.f);
            #pragma unroll 2
            for (int j = 0; j < 16; j++) {
                const int k = j * 32 + kq * 4;
                float4 tv[4];
                #pragma unroll
                for (int s = 0; s < 4; s++)
                    tv[s] = __ldcg((const float4*)(tl + (long)(ib + s) * INNER + k));
                #pragma unroll
                for (int kk = 0; kk < 4; kk++) {
                    float4 wv = wb4[(j * 4 + kk) * 32];
                    #pragma unroll
                    for (int s = 0; s < 4; s++) fma4(acc[s], fcomp(tv[s], kk), wv);
                }
            }
            #pragma unroll
            for (int s = 0; s < 4; s++) { red4(acc[s], 4); red4(acc[s], 8); red4(acc[s], 16); }
            __syncthreads();                    // gates visible
            if (lane < 4) {
                const int col = cb2 + lane * 4;
                float4 b1v = *(const float4*)&sb1[lane * 4];
                const float* xtp = (lvl2 == 0) ? &g_xe[(long)t2 * BB * HH]
                                               : r_xv[lvl2 - 1][t2 & 3];
                const float* hop = r_xv[lvl2][(t2 + 3) & 3];
                float* hnp = r_xv[lvl2][t2 & 3];
                #pragma unroll
                for (int s = 0; s < 4; s++) {
                    int i = ib + s;
                    float h0 = lrelu(acc[s].x + b1v.x);
                    float h1 = lrelu(acc[s].y + b1v.y);
                    float h2 = lrelu(acc[s].z + b1v.z);
                    float h3 = lrelu(acc[s].w + b1v.w);
                    float bo = sgb[i], xo = sgx[i], ho = sgh[i];
                    float4 xt4 = __ldcg((const float4*)&xtp[i * HH + col]);
                    float4 hl4 = __ldcg((const float4*)&hop[i * HH + col]);
                    float4 hn;
                    hn.x = bo * h0 + xo * xt4.x + ho * hl4.x;
                    hn.y = bo * h1 + xo * xt4.y + ho * hl4.y;
                    hn.z = bo * h2 + xo * xt4.z + ho * hl4.z;
                    hn.w = bo * h3 + xo * xt4.w + ho * hl4.w;
                    *(float4*)&hnp[i * HH + col] = hn;
                    if (lvl2 == LEVELS - 1 && t2 == SS - 1)
                        *(float4*)&out[i * HH + col] = hn;
                }
            }
            __syncthreads();
            if (tid == 0) { __threadfence(); atomicAdd(&cnt2[lvl2], 1u); }
        }
    }
}

extern "C" void kernel_launch(void* const* d_in, const int* in_sizes, int n_in,
                              void* d_out, int out_size) {
    const float* x     = (const float*)d_in[0];
    const float* mask  = (const float*)d_in[1];
    const float* W_emb = (const float*)d_in[3];
    const float* b_emb = (const float*)d_in[4];
    const float* W     = (const float*)d_in[5];
    const float* U     = (const float*)d_in[6];
    const float* b     = (const float*)d_in[7];
    const float* W1    = (const float*)d_in[8];
    const float* b1    = (const float*)d_in[9];
    const float* Wa1   = (const float*)d_in[10];
    const float* Ua1   = (const float*)d_in[11];
    const float* ba1   = (const float*)d_in[12];
    const float* Wa3   = (const float*)d_in[13];
    const float* ba3   = (const float*)d_in[14];
    float* out = (float*)d_out;

    cudaFuncSetAttribute(enc_kernel, cudaFuncAttributeMaxDynamicSharedMemorySize, SMEM_BYTES);
    enc_kernel<<<NB, NT, SMEM_BYTES>>>(x, mask, W_emb, b_emb, W, U, b, W1, b1,
                                       Wa1, Ua1, ba1, Wa3, ba3, out);
}